// round 3
// baseline (speedup 1.0000x reference)
#include <cuda_runtime.h>
#include <math.h>

#define NCLS 1000
#define NV4  250   // 1000 floats = 250 float4 per row

// Monotone float -> u32 map (order-preserving for all non-NaN floats)
__device__ __forceinline__ unsigned fmap(float x) {
    int i = __float_as_int(x);
    return (i < 0) ? ~(unsigned)i : ((unsigned)i | 0x80000000u);
}
__device__ __forceinline__ float funmap(unsigned u) {
    int i = (u & 0x80000000u) ? (int)(u & 0x7FFFFFFFu) : ~(int)u;
    return __int_as_float(i);
}

__device__ __forceinline__ void atomicMaxFloat(float* addr, float val) {
    int* ia = (int*)addr;
    int old = *ia;
    while (val > __int_as_float(old)) {
        int assumed = old;
        old = atomicCAS(ia, assumed, __float_as_int(val));
        if (old == assumed) break;
    }
}

__global__ void init_kernel(float* out_max) {
    if (threadIdx.x == 0) *out_max = -INFINITY;
}

__global__ __launch_bounds__(256, 4) void margin_kernel(
    const float* __restrict__ o1, const float* __restrict__ o2,
    const float* __restrict__ o3, const float* __restrict__ o4,
    const float* __restrict__ mim, const int* __restrict__ targets,
    float* __restrict__ out_max, float* __restrict__ out_thr)
{
    const int row = blockIdx.x;
    const int tid = threadIdx.x;
    const int t   = targets[row];           // int32
    const int town = t >> 2, tsub = t & 3;  // owning thread / sub-lane of target

    const float* mats[5] = {o1, o2, o3, o4, mim};

    __shared__ float    s_tgt[5];
    __shared__ unsigned s_red[5][8];

    // ---- load phase: 5 independent float4 loads per thread (MLP=5) ----
    float4 v[5];
    const bool active = (tid < NV4);
    if (active) {
        const size_t base = (size_t)row * NCLS;
        #pragma unroll
        for (int m = 0; m < 5; m++)
            v[m] = reinterpret_cast<const float4*>(mats[m] + base)[tid];
    }

    // ---- per-thread max (excluding target element) + target capture ----
    unsigned u[5];
    const bool own = (tid == town);
    #pragma unroll
    for (int m = 0; m < 5; m++) {
        float a = -INFINITY, b = -INFINITY, c = -INFINITY, d = -INFINITY;
        if (active) { a = v[m].x; b = v[m].y; c = v[m].z; d = v[m].w; }
        float mx = fmaxf(fmaxf(a, b), fmaxf(c, d));
        if (own) {   // only one thread per row: capture tgt value, exclude it
            float tv = (tsub == 0) ? a : (tsub == 1) ? b : (tsub == 2) ? c : d;
            s_tgt[m] = tv;
            float ea = (tsub == 0) ? -INFINITY : a;
            float eb = (tsub == 1) ? -INFINITY : b;
            float ec = (tsub == 2) ? -INFINITY : c;
            float ed = (tsub == 3) ? -INFINITY : d;
            mx = fmaxf(fmaxf(ea, eb), fmaxf(ec, ed));
        }
        u[m] = fmap(mx);
    }

    // ---- warp reduction: single REDUX per matrix ----
    #pragma unroll
    for (int m = 0; m < 5; m++)
        u[m] = __reduce_max_sync(0xFFFFFFFFu, u[m]);

    const int warp = tid >> 5, lane = tid & 31;
    if (lane == 0) {
        #pragma unroll
        for (int m = 0; m < 5; m++) s_red[m][warp] = u[m];
    }
    __syncthreads();

    // ---- final combine + softmax by thread 0 ----
    if (tid == 0) {
        float m_excl[5];
        #pragma unroll
        for (int m = 0; m < 5; m++) {
            unsigned um = s_red[m][0];
            #pragma unroll
            for (int w = 1; w < 8; w++) um = max(um, s_red[m][w]);
            m_excl[m] = funmap(um);
        }

        // global max over mats 0..3 (restore excluded target element)
        float g = -INFINITY;
        #pragma unroll
        for (int m = 0; m < 4; m++) g = fmaxf(g, fmaxf(m_excl[m], s_tgt[m]));
        atomicMaxFloat(out_max, g);

        // margin = max(0, tgt - max_excl), with /TEMPERATURE(=2) folded in
        float margin[5];
        #pragma unroll
        for (int m = 0; m < 5; m++)
            margin[m] = fmaxf(0.0f, (s_tgt[m] - m_excl[m]) * 0.5f);

        float mx = margin[0];
        #pragma unroll
        for (int m = 1; m < 5; m++) mx = fmaxf(mx, margin[m]);
        float e[5], s = 0.0f;
        #pragma unroll
        for (int m = 0; m < 5; m++) { e[m] = __expf(margin[m] - mx); s += e[m]; }
        float inv = 1.0f / s;
        float* dst = out_thr + (size_t)row * 5;
        #pragma unroll
        for (int m = 0; m < 5; m++) dst[m] = e[m] * inv;
    }
}

extern "C" void kernel_launch(void* const* d_in, const int* in_sizes, int n_in,
                              void* d_out, int out_size)
{
    const float* o1  = (const float*)d_in[0];
    const float* o2  = (const float*)d_in[1];
    const float* o3  = (const float*)d_in[2];
    const float* o4  = (const float*)d_in[3];
    const float* mim = (const float*)d_in[4];
    const int*   tgt = (const int*)d_in[5];

    const int n = in_sizes[5];          // 16384 rows
    float* out = (float*)d_out;

    float* out_thr = out + ((size_t)out_size - (size_t)n * 5);
    float* out_max = out;

    init_kernel<<<1, 32>>>(out_max);
    margin_kernel<<<n, 256>>>(o1, o2, o3, o4, mim, tgt, out_max, out_thr);
}

// round 4
// speedup vs baseline: 1.4198x; 1.4198x over previous
#include <cuda_runtime.h>
#include <math.h>

#define NCLS 1000
#define NV4  250   // 1000 floats = 250 float4 per row

// Monotone float -> u32 map (order-preserving for all non-NaN floats)
__device__ __forceinline__ unsigned fmap(float x) {
    int i = __float_as_int(x);
    return (i < 0) ? ~(unsigned)i : ((unsigned)i | 0x80000000u);
}
__device__ __forceinline__ float funmap(unsigned u) {
    int i = (u & 0x80000000u) ? (int)(u & 0x7FFFFFFFu) : ~(int)u;
    return __int_as_float(i);
}

__device__ __forceinline__ void atomicMaxFloat(float* addr, float val) {
    int* ia = (int*)addr;
    int old = *ia;
    while (val > __int_as_float(old)) {
        int assumed = old;
        old = atomicCAS(ia, assumed, __float_as_int(val));
        if (old == assumed) break;
    }
}

__global__ void init_kernel(float* out_max) {
    if (threadIdx.x == 0) *out_max = -INFINITY;
}

__global__ __launch_bounds__(256, 8) void margin_kernel(
    const float* __restrict__ o1, const float* __restrict__ o2,
    const float* __restrict__ o3, const float* __restrict__ o4,
    const float* __restrict__ mim, const int* __restrict__ targets,
    float* __restrict__ out_max, float* __restrict__ out_thr)
{
    const int row = blockIdx.x;
    const int tid = threadIdx.x;
    const int t   = targets[row];           // int32
    const int town = t >> 2, tsub = t & 3;  // owning thread / sub-lane of target

    const float* mats[5] = {o1, o2, o3, o4, mim};

    __shared__ float    s_tgt[5];
    __shared__ unsigned s_red[5][8];

    // ---- load phase: 5 independent streaming float4 loads per thread ----
    float4 v[5];
    const bool active = (tid < NV4);
    if (active) {
        const size_t base = (size_t)row * NCLS;
        #pragma unroll
        for (int m = 0; m < 5; m++)
            v[m] = __ldcs(reinterpret_cast<const float4*>(mats[m] + base) + tid);
    }

    // ---- per-thread max (excluding target element) + target capture ----
    unsigned u[5];
    const bool own = (tid == town);
    #pragma unroll
    for (int m = 0; m < 5; m++) {
        float a = -INFINITY, b = -INFINITY, c = -INFINITY, d = -INFINITY;
        if (active) { a = v[m].x; b = v[m].y; c = v[m].z; d = v[m].w; }
        float mx = fmaxf(fmaxf(a, b), fmaxf(c, d));
        if (own) {   // one thread per row: capture tgt value, exclude it
            float tv = (tsub == 0) ? a : (tsub == 1) ? b : (tsub == 2) ? c : d;
            s_tgt[m] = tv;
            float ea = (tsub == 0) ? -INFINITY : a;
            float eb = (tsub == 1) ? -INFINITY : b;
            float ec = (tsub == 2) ? -INFINITY : c;
            float ed = (tsub == 3) ? -INFINITY : d;
            mx = fmaxf(fmaxf(ea, eb), fmaxf(ec, ed));
        }
        u[m] = fmap(mx);
    }

    // ---- warp reduction: single REDUX per matrix ----
    #pragma unroll
    for (int m = 0; m < 5; m++)
        u[m] = __reduce_max_sync(0xFFFFFFFFu, u[m]);

    const int warp = tid >> 5, lane = tid & 31;
    if (lane == 0) {
        #pragma unroll
        for (int m = 0; m < 5; m++) s_red[m][warp] = u[m];
    }
    __syncthreads();

    // ---- final combine + softmax by thread 0 ----
    if (tid == 0) {
        float m_excl[5];
        #pragma unroll
        for (int m = 0; m < 5; m++) {
            unsigned um = s_red[m][0];
            #pragma unroll
            for (int w = 1; w < 8; w++) um = max(um, s_red[m][w]);
            m_excl[m] = funmap(um);
        }

        // global max over mats 0..3 (restore excluded target element)
        float g = -INFINITY;
        #pragma unroll
        for (int m = 0; m < 4; m++) g = fmaxf(g, fmaxf(m_excl[m], s_tgt[m]));
        atomicMaxFloat(out_max, g);

        // margin = max(0, tgt - max_excl), with /TEMPERATURE(=2) folded in
        float margin[5];
        #pragma unroll
        for (int m = 0; m < 5; m++)
            margin[m] = fmaxf(0.0f, (s_tgt[m] - m_excl[m]) * 0.5f);

        float mx = margin[0];
        #pragma unroll
        for (int m = 1; m < 5; m++) mx = fmaxf(mx, margin[m]);
        float e[5], s = 0.0f;
        #pragma unroll
        for (int m = 0; m < 5; m++) { e[m] = __expf(margin[m] - mx); s += e[m]; }
        float inv = 1.0f / s;
        float* dst = out_thr + (size_t)row * 5;
        #pragma unroll
        for (int m = 0; m < 5; m++) dst[m] = e[m] * inv;
    }
}

extern "C" void kernel_launch(void* const* d_in, const int* in_sizes, int n_in,
                              void* d_out, int out_size)
{
    const float* o1  = (const float*)d_in[0];
    const float* o2  = (const float*)d_in[1];
    const float* o3  = (const float*)d_in[2];
    const float* o4  = (const float*)d_in[3];
    const float* mim = (const float*)d_in[4];
    const int*   tgt = (const int*)d_in[5];

    const int n = in_sizes[5];          // 16384 rows
    float* out = (float*)d_out;

    float* out_thr = out + ((size_t)out_size - (size_t)n * 5);
    float* out_max = out;

    init_kernel<<<1, 32>>>(out_max);
    margin_kernel<<<n, 256>>>(o1, o2, o3, o4, mim, tgt, out_max, out_thr);
}

// round 5
// speedup vs baseline: 1.4365x; 1.0118x over previous
#include <cuda_runtime.h>
#include <math.h>

#define NCLS 1000
#define NV4  250   // 1000 floats = 250 float4 per row

// Monotone float -> u32 map (order-preserving for all non-NaN floats).
// All encoded values are >= 0x00000001 region; 0 acts as "bottom" identity.
__device__ __forceinline__ unsigned fmap(float x) {
    int i = __float_as_int(x);
    return (i < 0) ? ~(unsigned)i : ((unsigned)i | 0x80000000u);
}
__device__ __forceinline__ float funmap(unsigned u) {
    int i = (u & 0x80000000u) ? (int)(u & 0x7FFFFFFFu) : ~(int)u;
    return __int_as_float(i);
}

// Self-resetting cross-launch scratch: zero at module load; the last block of
// every launch resets both to zero, so every launch sees identical state.
__device__ unsigned g_gmax  = 0;
__device__ unsigned g_count = 0;

__global__ __launch_bounds__(256, 8) void margin_kernel(
    const float* __restrict__ o1, const float* __restrict__ o2,
    const float* __restrict__ o3, const float* __restrict__ o4,
    const float* __restrict__ mim, const int* __restrict__ targets,
    float* __restrict__ out_max, float* __restrict__ out_thr)
{
    const int row = blockIdx.x;
    const int tid = threadIdx.x;
    const int t   = targets[row];           // int32
    const int town = t >> 2, tsub = t & 3;  // owning thread / sub-lane of target

    const float* mats[5] = {o1, o2, o3, o4, mim};

    __shared__ float    s_tgt[5];
    __shared__ unsigned s_red[5][8];

    // ---- load phase: 5 independent streaming float4 loads per thread ----
    float4 v[5];
    const bool active = (tid < NV4);
    if (active) {
        const size_t base = (size_t)row * NCLS;
        #pragma unroll
        for (int m = 0; m < 5; m++)
            v[m] = __ldcs(reinterpret_cast<const float4*>(mats[m] + base) + tid);
    }

    // ---- per-thread max (excluding target element) + target capture ----
    unsigned u[5];
    const bool own = (tid == town);
    #pragma unroll
    for (int m = 0; m < 5; m++) {
        float a = -INFINITY, b = -INFINITY, c = -INFINITY, d = -INFINITY;
        if (active) { a = v[m].x; b = v[m].y; c = v[m].z; d = v[m].w; }
        float mx = fmaxf(fmaxf(a, b), fmaxf(c, d));
        if (own) {   // one thread per row: capture tgt value, exclude it
            float tv = (tsub == 0) ? a : (tsub == 1) ? b : (tsub == 2) ? c : d;
            s_tgt[m] = tv;
            float ea = (tsub == 0) ? -INFINITY : a;
            float eb = (tsub == 1) ? -INFINITY : b;
            float ec = (tsub == 2) ? -INFINITY : c;
            float ed = (tsub == 3) ? -INFINITY : d;
            mx = fmaxf(fmaxf(ea, eb), fmaxf(ec, ed));
        }
        u[m] = fmap(mx);
    }

    // ---- warp reduction: single REDUX per matrix ----
    #pragma unroll
    for (int m = 0; m < 5; m++)
        u[m] = __reduce_max_sync(0xFFFFFFFFu, u[m]);

    const int warp = tid >> 5, lane = tid & 31;
    if (lane == 0) {
        #pragma unroll
        for (int m = 0; m < 5; m++) s_red[m][warp] = u[m];
    }
    __syncthreads();

    // ---- final combine + softmax + global-max protocol by thread 0 ----
    if (tid == 0) {
        float m_excl[5];
        #pragma unroll
        for (int m = 0; m < 5; m++) {
            unsigned um = s_red[m][0];
            #pragma unroll
            for (int w = 1; w < 8; w++) um = max(um, s_red[m][w]);
            m_excl[m] = funmap(um);
        }

        // row max over mats 0..3 (restore excluded target element)
        float g = -INFINITY;
        #pragma unroll
        for (int m = 0; m < 4; m++) g = fmaxf(g, fmaxf(m_excl[m], s_tgt[m]));

        // margin = max(0, tgt - max_excl), with /TEMPERATURE(=2) folded in
        float margin[5];
        #pragma unroll
        for (int m = 0; m < 5; m++)
            margin[m] = fmaxf(0.0f, (s_tgt[m] - m_excl[m]) * 0.5f);

        float mx = margin[0];
        #pragma unroll
        for (int m = 1; m < 5; m++) mx = fmaxf(mx, margin[m]);
        float e[5], s = 0.0f;
        #pragma unroll
        for (int m = 0; m < 5; m++) { e[m] = __expf(margin[m] - mx); s += e[m]; }
        float inv = 1.0f / s;
        float* dst = out_thr + (size_t)row * 5;
        #pragma unroll
        for (int m = 0; m < 5; m++) dst[m] = e[m] * inv;

        // ---- global max: atomic accumulate, last block publishes + resets ----
        atomicMax(&g_gmax, fmap(g));
        __threadfence();
        unsigned c = atomicAdd(&g_count, 1);
        if (c == gridDim.x - 1) {          // last block to finish
            unsigned final_u = atomicMax(&g_gmax, 0u);  // atomic read
            *out_max = funmap(final_u);
            // reset scratch for the next (graph-replayed) launch
            atomicExch(&g_gmax, 0u);
            atomicExch(&g_count, 0u);
        }
    }
}

extern "C" void kernel_launch(void* const* d_in, const int* in_sizes, int n_in,
                              void* d_out, int out_size)
{
    const float* o1  = (const float*)d_in[0];
    const float* o2  = (const float*)d_in[1];
    const float* o3  = (const float*)d_in[2];
    const float* o4  = (const float*)d_in[3];
    const float* mim = (const float*)d_in[4];
    const int*   tgt = (const int*)d_in[5];

    const int n = in_sizes[5];          // 16384 rows
    float* out = (float*)d_out;

    float* out_thr = out + ((size_t)out_size - (size_t)n * 5);
    float* out_max = out;

    margin_kernel<<<n, 256>>>(o1, o2, o3, o4, mim, tgt, out_max, out_thr);
}